// round 1
// baseline (speedup 1.0000x reference)
#include <cuda_runtime.h>
#include <cuda_bf16.h>

// Problem: y = x.reshape(64, 786432) @ W^T + b ; top-k(2) scatter ; softmax(64)
//   x: [64, 786432] f32, W: [64, 786432] f32, b: [64] f32, k: int (=2)
//   out: [64, 64] f32
//
// Kernel 1: split-K GEMM. 512 CTAs, each computes the full 64x64 output tile
//           over a K-slice of 1536 (x, W each read exactly once from HBM).
// Kernel 2: reduce partials + bias + rank-based top-k + softmax.

#define K_TOTAL 786432
#define NBLK    512
#define KCHUNK  (K_TOTAL / NBLK)   // 1536
#define KC      32                 // smem tile depth
#define NTILES  (KCHUNK / KC)      // 48
#define PAD     68                 // row stride (floats) in smem: 16B-aligned float4
                                   // reads + low-conflict transpose stores

__device__ float g_partials[NBLK * 64 * 64];  // 8 MB scratch

__global__ __launch_bounds__(256) void gemm_partial_kernel(
    const float* __restrict__ x, const float* __restrict__ W) {
    __shared__ float xs[KC][PAD];
    __shared__ float ws[KC][PAD];

    const int tid = threadIdx.x;          // 256 threads
    const int tx  = tid & 15;             // batch group  (4 rows each)
    const int ty  = tid >> 4;             // expert group (4 rows each)

    const long kbase = (long)blockIdx.x * KCHUNK;

    // Loader mapping: tile is 64 rows x 8 float4-quads = 512 float4 per matrix.
    // Thread handles quads idx=tid and idx=tid+256.
    const int r0 = tid >> 3;              // rows 0..31
    const int q0 = tid & 7;
    const int r1 = (tid + 256) >> 3;      // rows 32..63
    const int q1 = q0;                    // (tid+256)&7 == tid&7

    const float* xp0 = x + (long)r0 * K_TOTAL + kbase + q0 * 4;
    const float* xp1 = x + (long)r1 * K_TOTAL + kbase + q1 * 4;
    const float* wp0 = W + (long)r0 * K_TOTAL + kbase + q0 * 4;
    const float* wp1 = W + (long)r1 * K_TOTAL + kbase + q1 * 4;

    float acc[4][4];
#pragma unroll
    for (int i = 0; i < 4; ++i)
#pragma unroll
        for (int j = 0; j < 4; ++j) acc[i][j] = 0.0f;

    // Prefetch first tile into registers.
    float4 px0 = *(const float4*)(xp0);
    float4 px1 = *(const float4*)(xp1);
    float4 pw0 = *(const float4*)(wp0);
    float4 pw1 = *(const float4*)(wp1);

    for (int t = 0; t < NTILES; ++t) {
        __syncthreads();  // previous tile's compute reads are done

        // Transposed store: smem layout [k][row]
        xs[q0 * 4 + 0][r0] = px0.x;  xs[q0 * 4 + 1][r0] = px0.y;
        xs[q0 * 4 + 2][r0] = px0.z;  xs[q0 * 4 + 3][r0] = px0.w;
        xs[q1 * 4 + 0][r1] = px1.x;  xs[q1 * 4 + 1][r1] = px1.y;
        xs[q1 * 4 + 2][r1] = px1.z;  xs[q1 * 4 + 3][r1] = px1.w;
        ws[q0 * 4 + 0][r0] = pw0.x;  ws[q0 * 4 + 1][r0] = pw0.y;
        ws[q0 * 4 + 2][r0] = pw0.z;  ws[q0 * 4 + 3][r0] = pw0.w;
        ws[q1 * 4 + 0][r1] = pw1.x;  ws[q1 * 4 + 1][r1] = pw1.y;
        ws[q1 * 4 + 2][r1] = pw1.z;  ws[q1 * 4 + 3][r1] = pw1.w;

        __syncthreads();

        // Prefetch next tile (overlaps LDG latency with FMA compute below).
        if (t + 1 < NTILES) {
            const long off = (long)(t + 1) * KC;
            px0 = *(const float4*)(xp0 + off);
            px1 = *(const float4*)(xp1 + off);
            pw0 = *(const float4*)(wp0 + off);
            pw1 = *(const float4*)(wp1 + off);
        }

#pragma unroll
        for (int kk = 0; kk < KC; ++kk) {
            // 16B-aligned, conflict-free (broadcast across same-tx / same-ty lanes)
            float4 a = *(const float4*)&xs[kk][tx * 4];
            float4 bfr = *(const float4*)&ws[kk][ty * 4];
            acc[0][0] = fmaf(a.x, bfr.x, acc[0][0]);
            acc[0][1] = fmaf(a.x, bfr.y, acc[0][1]);
            acc[0][2] = fmaf(a.x, bfr.z, acc[0][2]);
            acc[0][3] = fmaf(a.x, bfr.w, acc[0][3]);
            acc[1][0] = fmaf(a.y, bfr.x, acc[1][0]);
            acc[1][1] = fmaf(a.y, bfr.y, acc[1][1]);
            acc[1][2] = fmaf(a.y, bfr.z, acc[1][2]);
            acc[1][3] = fmaf(a.y, bfr.w, acc[1][3]);
            acc[2][0] = fmaf(a.z, bfr.x, acc[2][0]);
            acc[2][1] = fmaf(a.z, bfr.y, acc[2][1]);
            acc[2][2] = fmaf(a.z, bfr.z, acc[2][2]);
            acc[2][3] = fmaf(a.z, bfr.w, acc[2][3]);
            acc[3][0] = fmaf(a.w, bfr.x, acc[3][0]);
            acc[3][1] = fmaf(a.w, bfr.y, acc[3][1]);
            acc[3][2] = fmaf(a.w, bfr.z, acc[3][2]);
            acc[3][3] = fmaf(a.w, bfr.w, acc[3][3]);
        }
    }

    // Write the per-CTA partial 64x64 tile.
    float* dst = g_partials + (long)blockIdx.x * 4096;
#pragma unroll
    for (int i = 0; i < 4; ++i) {
        const int b = tx * 4 + i;
#pragma unroll
        for (int j = 0; j < 4; ++j) {
            const int e = ty * 4 + j;
            dst[b * 64 + e] = acc[i][j];
        }
    }
}

__global__ __launch_bounds__(256) void finalize_kernel(
    const float* __restrict__ bias, const int* __restrict__ kp,
    float* __restrict__ out) {
    const int b    = blockIdx.x;     // batch row, 64 blocks
    const int t    = threadIdx.x;    // 256 threads
    const int e    = t & 63;         // expert
    const int part = t >> 6;         // 0..3

    // Reduce 512 partials: 4 threads per expert, coalesced over e.
    float s = 0.0f;
#pragma unroll 4
    for (int c = part; c < NBLK; c += 4)
        s += g_partials[(long)c * 4096 + b * 64 + e];

    __shared__ float acc4[4][64];
    __shared__ float ys[64];
    __shared__ float evs[64];

    acc4[part][e] = s;
    __syncthreads();
    if (part == 0)
        ys[e] = acc4[0][e] + acc4[1][e] + acc4[2][e] + acc4[3][e] + bias[e];
    __syncthreads();

    // Rank of y[e] among 64 logits (ties broken by lower index, matching top_k).
    const float yv = ys[e];
    const int kk = *kp;
    int rank = 0;
#pragma unroll 8
    for (int j = 0; j < 64; ++j) {
        const float yj = ys[j];
        rank += (yj > yv) || (yj == yv && j < e);
    }
    // softmax of scatter(topk): non-topk entries are exp(0) = 1
    const float ev = (rank < kk) ? expf(yv) : 1.0f;
    if (part == 0) evs[e] = ev;
    __syncthreads();

    // Tree-reduce denominator over 64 values.
    for (int off = 32; off > 0; off >>= 1) {
        if (t < off) evs[t] += evs[t + off];
        __syncthreads();
    }
    const float denom = evs[0];

    if (part == 0) out[b * 64 + e] = ev / denom;
}

extern "C" void kernel_launch(void* const* d_in, const int* in_sizes, int n_in,
                              void* d_out, int out_size) {
    const float* x    = (const float*)d_in[0];
    const float* W    = (const float*)d_in[1];
    const float* bias = (const float*)d_in[2];
    const int*   kp   = (const int*)d_in[3];
    float* out = (float*)d_out;

    gemm_partial_kernel<<<NBLK, 256>>>(x, W);
    finalize_kernel<<<64, 256>>>(bias, kp, out);
}

// round 3
// speedup vs baseline: 2.5846x; 2.5846x over previous
#include <cuda_runtime.h>
#include <cuda_bf16.h>
#include <cstdint>

// TopKRoute: y = x.reshape(64, 786432) @ W^T + b ; scatter top-k ; softmax(64)
//   x: [64, 786432] f32, W: [64, 786432] f32, b: [64] f32, k: int (=2)
//   out: [64, 64] f32
//
// Round 3: split-precision bf16 GEMM on the portable mma.sync path
// (tcgen05 is sm_103a-gated at PTX level; this harness targets compute_103).
//   x = xh + xl, W = wh + wl (bf16 hi + bf16 residual).
//   acc += xh*wh + xh*wl + xl*wh   (xl*wl dropped: O(2^-18) relative)
//   256 CTAs, each computes the full 64x64 tile over a K-slice of 3072.
//   x, W each read exactly once from HBM: 403 MB -> ~51 us floor @ 8 TB/s.

#define K_TOTAL 786432
#define NBLK    256
#define KCHUNK  (K_TOTAL / NBLK)   // 3072
#define KC      64                 // k per smem tile (64 bf16 = 128B = SW128 row)
#define NT      (KCHUNK / KC)      // 48 tiles per CTA

__device__ float g_partials[NBLK * 64 * 64];  // 4 MB scratch

// ---------------- helpers ----------------

__device__ __forceinline__ uint32_t smem_u32(const void* p) {
    return (uint32_t)__cvta_generic_to_shared(p);
}

__device__ __forceinline__ void ldsm4(uint32_t* r, uint32_t addr) {
    asm volatile("ldmatrix.sync.aligned.m8n8.x4.shared.b16 {%0,%1,%2,%3}, [%4];"
                 : "=r"(r[0]), "=r"(r[1]), "=r"(r[2]), "=r"(r[3]) : "r"(addr));
}

__device__ __forceinline__ void mma16816(float* c, const uint32_t* a,
                                         uint32_t b0, uint32_t b1) {
    asm volatile(
        "mma.sync.aligned.m16n8k16.row.col.f32.bf16.bf16.f32 "
        "{%0,%1,%2,%3}, {%4,%5,%6,%7}, {%8,%9}, {%0,%1,%2,%3};"
        : "+f"(c[0]), "+f"(c[1]), "+f"(c[2]), "+f"(c[3])
        : "r"(a[0]), "r"(a[1]), "r"(a[2]), "r"(a[3]), "r"(b0), "r"(b1));
}

// Split float4 into packed bf16 hi pairs and residual-lo pairs.
__device__ __forceinline__ void split4(float4 v, uint2& hi, uint2& lo) {
    __nv_bfloat162 h0 = __float22bfloat162_rn(make_float2(v.x, v.y));
    __nv_bfloat162 h1 = __float22bfloat162_rn(make_float2(v.z, v.w));
    float2 f0 = __bfloat1622float2(h0);
    float2 f1 = __bfloat1622float2(h1);
    __nv_bfloat162 l0 = __float22bfloat162_rn(make_float2(v.x - f0.x, v.y - f0.y));
    __nv_bfloat162 l1 = __float22bfloat162_rn(make_float2(v.z - f1.x, v.w - f1.y));
    hi.x = *(uint32_t*)&h0;  hi.y = *(uint32_t*)&h1;
    lo.x = *(uint32_t*)&l0;  lo.y = *(uint32_t*)&l1;
}

__device__ __forceinline__ uint32_t sw128(uint32_t off) {
    return off ^ ((off >> 3) & 0x70);
}

// ---------------- GEMM kernel ----------------

struct Smem {
    alignas(1024) char xh[64 * 128];
    alignas(1024) char xl[64 * 128];
    alignas(1024) char wh[64 * 128];
    alignas(1024) char wl[64 * 128];
};

__global__ __launch_bounds__(256, 2) void gemm_mma_kernel(
    const float* __restrict__ x, const float* __restrict__ W) {
    __shared__ Smem s;

    const int tid  = threadIdx.x;
    const int wid  = tid >> 5;
    const int lane = tid & 31;

    // Loader mapping: per matrix per tile 64 rows x 16 float4; thread handles
    // (row = (tid>>4) + 16*i, q = tid&15), i = 0..3. Coalesced over q.
    const int q     = tid & 15;
    const int rbase = tid >> 4;
    const long kbase = (long)blockIdx.x * KCHUNK;

    const float* px[4];
    const float* pw[4];
    uint32_t soff[4];
#pragma unroll
    for (int i = 0; i < 4; ++i) {
        const int row = rbase + 16 * i;
        px[i] = x + (long)row * K_TOTAL + kbase + q * 4;
        pw[i] = W + (long)row * K_TOTAL + kbase + q * 4;
        soff[i] = sw128((uint32_t)(row * 128 + q * 8));
    }

    // Warp tiling: 4 row-groups x 2 col-groups. Warp computes 16 rows x 32 cols.
    const int r0 = (wid & 3) * 16;
    const int cw = (wid >> 2) * 32;

    // ldmatrix lane addressing: rows via lane&15, k-halves via lane>>4.
    const int arow = r0 + (lane & 15);
    const int br0  = cw + (lane & 15);        // B cols cw..cw+15
    const int br1  = cw + 16 + (lane & 15);   // B cols cw+16..cw+31
    const uint32_t khi   = (uint32_t)((lane >> 4) * 16);
    const uint32_t axm   = (uint32_t)((arow & 7) * 16);
    const uint32_t bxm0  = (uint32_t)((br0 & 7) * 16);
    const uint32_t bxm1  = (uint32_t)((br1 & 7) * 16);
    const uint32_t a_base  = smem_u32(s.xh) + (uint32_t)(arow * 128);
    const uint32_t al_base = smem_u32(s.xl) + (uint32_t)(arow * 128);
    const uint32_t b0h_base = smem_u32(s.wh) + (uint32_t)(br0 * 128);
    const uint32_t b1h_base = smem_u32(s.wh) + (uint32_t)(br1 * 128);
    const uint32_t b0l_base = smem_u32(s.wl) + (uint32_t)(br0 * 128);
    const uint32_t b1l_base = smem_u32(s.wl) + (uint32_t)(br1 * 128);

    float acc[4][4];
#pragma unroll
    for (int i = 0; i < 4; ++i)
#pragma unroll
        for (int j = 0; j < 4; ++j) acc[i][j] = 0.0f;

    // Prefetch tile 0 into registers.
    float4 rx[4], rw[4];
#pragma unroll
    for (int i = 0; i < 4; ++i) {
        rx[i] = *(const float4*)(px[i]);
        rw[i] = *(const float4*)(pw[i]);
    }

    for (int t = 0; t < NT; ++t) {
        if (t > 0) __syncthreads();   // previous tile's ldmatrix reads done

        // Convert + store into smem tiles.
#pragma unroll
        for (int i = 0; i < 4; ++i) {
            uint2 hi, lo;
            split4(rx[i], hi, lo);
            *(uint2*)(s.xh + soff[i]) = hi;
            *(uint2*)(s.xl + soff[i]) = lo;
            split4(rw[i], hi, lo);
            *(uint2*)(s.wh + soff[i]) = hi;
            *(uint2*)(s.wl + soff[i]) = lo;
        }
        __syncthreads();

        // Prefetch next tile (LDG latency overlaps MMA compute below).
        if (t + 1 < NT) {
            const long off = (long)(t + 1) * KC;
#pragma unroll
            for (int i = 0; i < 4; ++i) {
                rx[i] = *(const float4*)(px[i] + off);
                rw[i] = *(const float4*)(pw[i] + off);
            }
        }

#pragma unroll
        for (int ks = 0; ks < 4; ++ks) {
            const uint32_t kterm = (uint32_t)(ks * 32) + khi;
            uint32_t ah[4], al[4], bh0[4], bh1[4], bl0[4], bl1[4];
            ldsm4(ah,  a_base   + (kterm ^ axm));
            ldsm4(al,  al_base  + (kterm ^ axm));
            ldsm4(bh0, b0h_base + (kterm ^ bxm0));
            ldsm4(bh1, b1h_base + (kterm ^ bxm1));
            ldsm4(bl0, b0l_base + (kterm ^ bxm0));
            ldsm4(bl1, b1l_base + (kterm ^ bxm1));

            // n-tiles: 0 -> (bh0[0],bh0[2]); 1 -> (bh0[1],bh0[3]);
            //          2 -> (bh1[0],bh1[2]); 3 -> (bh1[1],bh1[3])
            mma16816(acc[0], ah, bh0[0], bh0[2]);
            mma16816(acc[1], ah, bh0[1], bh0[3]);
            mma16816(acc[2], ah, bh1[0], bh1[2]);
            mma16816(acc[3], ah, bh1[1], bh1[3]);

            mma16816(acc[0], ah, bl0[0], bl0[2]);
            mma16816(acc[1], ah, bl0[1], bl0[3]);
            mma16816(acc[2], ah, bl1[0], bl1[2]);
            mma16816(acc[3], ah, bl1[1], bl1[3]);

            mma16816(acc[0], al, bh0[0], bh0[2]);
            mma16816(acc[1], al, bh0[1], bh0[3]);
            mma16816(acc[2], al, bh1[0], bh1[2]);
            mma16816(acc[3], al, bh1[1], bh1[3]);
        }
    }

    // Epilogue: write this CTA's 64x64 partial tile.
    // c-fragment: lane holds rows r0+(lane>>2), r0+8+(lane>>2); cols 2*(lane&3), +1.
    float* dst = g_partials + (long)blockIdx.x * 4096;
    const int gr = lane >> 2;
    const int gc = (lane & 3) * 2;
#pragma unroll
    for (int ti = 0; ti < 4; ++ti) {
        const int e = cw + ti * 8 + gc;
        *(float2*)&dst[(r0 + gr) * 64 + e]     = make_float2(acc[ti][0], acc[ti][1]);
        *(float2*)&dst[(r0 + 8 + gr) * 64 + e] = make_float2(acc[ti][2], acc[ti][3]);
    }
}

// ---------------- Finalize: reduce + bias + top-k + softmax ----------------

__global__ __launch_bounds__(512) void finalize_kernel(
    const float* __restrict__ bias, const int* __restrict__ kp,
    float* __restrict__ out) {
    const int b    = blockIdx.x;    // batch row
    const int t    = threadIdx.x;   // 512 threads
    const int e    = t & 63;        // expert
    const int part = t >> 6;        // 0..7

    float sum = 0.0f;
    const float* p = g_partials + (long)part * 4096 + b * 64 + e;
#pragma unroll 8
    for (int i = 0; i < NBLK / 8; ++i)
        sum += p[(long)i * 8 * 4096];

    __shared__ float acc[8][64];
    __shared__ float ys[64];
    __shared__ float evs[64];

    acc[part][e] = sum;
    __syncthreads();
    if (part == 0) {
        float s2 = 0.0f;
#pragma unroll
        for (int j = 0; j < 8; ++j) s2 += acc[j][e];
        ys[e] = s2 + bias[e];
    }
    __syncthreads();

    const float yv = ys[e];
    const int kk = *kp;
    int rank = 0;
#pragma unroll 8
    for (int j = 0; j < 64; ++j) {
        const float yj = ys[j];
        rank += (yj > yv) || (yj == yv && j < e);
    }
    const float ev = (rank < kk) ? expf(yv) : 1.0f;
    if (part == 0) evs[e] = ev;
    __syncthreads();

    for (int off = 32; off > 0; off >>= 1) {
        if (t < off) evs[t] += evs[t + off];
        __syncthreads();
    }
    const float denom = evs[0];

    if (part == 0) out[b * 64 + e] = ev / denom;
}

extern "C" void kernel_launch(void* const* d_in, const int* in_sizes, int n_in,
                              void* d_out, int out_size) {
    const float* x    = (const float*)d_in[0];
    const float* W    = (const float*)d_in[1];
    const float* bias = (const float*)d_in[2];
    const int*   kp   = (const int*)d_in[3];
    float* out = (float*)d_out;

    gemm_mma_kernel<<<NBLK, 256>>>(x, W);
    finalize_kernel<<<64, 512>>>(bias, kp, out);
}

// round 4
// speedup vs baseline: 2.9869x; 1.1557x over previous
#include <cuda_runtime.h>
#include <cuda_bf16.h>
#include <cstdint>

// TopKRoute: y = x.reshape(64, 786432) @ W^T + b ; scatter top-k ; softmax(64)
// Round 4: split-precision bf16 mma.sync GEMM, balanced 296-CTA grid,
// double-buffered smem (1 barrier/tile), 2x2x2 warp tiling (32x32 x k-half).

#define K_TOTAL     786432
#define NBLK        296
#define TILE_K      64
#define TILES_TOTAL (K_TOTAL / TILE_K)        // 12288
#define BASE_T      (TILES_TOTAL / NBLK)      // 41
#define EXTRA_T     (TILES_TOTAL % NBLK)      // 152

// dynamic smem: two 32KB buffers; regions within a buffer:
#define XH_OFF 0
#define XL_OFF 8192
#define WH_OFF 16384
#define WL_OFF 24576
#define BUF_BYTES 32768

__device__ float g_partials[NBLK * 64 * 64];   // 4.85 MB scratch

// ---------------- helpers ----------------

__device__ __forceinline__ uint32_t smem_u32(const void* p) {
    return (uint32_t)__cvta_generic_to_shared(p);
}

__device__ __forceinline__ void ldsm4(uint32_t* r, uint32_t addr) {
    asm volatile("ldmatrix.sync.aligned.m8n8.x4.shared.b16 {%0,%1,%2,%3}, [%4];"
                 : "=r"(r[0]), "=r"(r[1]), "=r"(r[2]), "=r"(r[3]) : "r"(addr));
}

__device__ __forceinline__ void mma16816(float* c, const uint32_t* a,
                                         uint32_t b0, uint32_t b1) {
    asm volatile(
        "mma.sync.aligned.m16n8k16.row.col.f32.bf16.bf16.f32 "
        "{%0,%1,%2,%3}, {%4,%5,%6,%7}, {%8,%9}, {%0,%1,%2,%3};"
        : "+f"(c[0]), "+f"(c[1]), "+f"(c[2]), "+f"(c[3])
        : "r"(a[0]), "r"(a[1]), "r"(a[2]), "r"(a[3]), "r"(b0), "r"(b1));
}

__device__ __forceinline__ void split4(float4 v, uint2& hi, uint2& lo) {
    __nv_bfloat162 h0 = __float22bfloat162_rn(make_float2(v.x, v.y));
    __nv_bfloat162 h1 = __float22bfloat162_rn(make_float2(v.z, v.w));
    float2 f0 = __bfloat1622float2(h0);
    float2 f1 = __bfloat1622float2(h1);
    __nv_bfloat162 l0 = __float22bfloat162_rn(make_float2(v.x - f0.x, v.y - f0.y));
    __nv_bfloat162 l1 = __float22bfloat162_rn(make_float2(v.z - f1.x, v.w - f1.y));
    hi.x = *(uint32_t*)&h0;  hi.y = *(uint32_t*)&h1;
    lo.x = *(uint32_t*)&l0;  lo.y = *(uint32_t*)&l1;
}

__device__ __forceinline__ uint32_t sw128(uint32_t off) {
    return off ^ ((off >> 3) & 0x70);
}

// ---------------- GEMM kernel ----------------

extern __shared__ char dsmem[];

__global__ __launch_bounds__(256, 2) void gemm_mma_kernel(
    const float* __restrict__ x, const float* __restrict__ W) {
    const int tid  = threadIdx.x;
    const int wid  = tid >> 5;
    const int lane = tid & 31;
    const int bid  = blockIdx.x;

    // Tile range for this CTA (balanced 41/42 split).
    const int t0  = BASE_T * bid + (bid < EXTRA_T ? bid : EXTRA_T);
    const int cnt = BASE_T + (bid < EXTRA_T ? 1 : 0);
    const long kbase = (long)t0 * TILE_K;

    // ---- loader mapping: 64 rows x 16 float4 per matrix per tile ----
    const int q     = tid & 15;
    const int rbase = tid >> 4;

    const float* px[4];
    const float* pw[4];
    uint32_t soff[4];
#pragma unroll
    for (int i = 0; i < 4; ++i) {
        const int row = rbase + 16 * i;
        px[i] = x + (long)row * K_TOTAL + kbase + q * 4;
        pw[i] = W + (long)row * K_TOTAL + kbase + q * 4;
        soff[i] = sw128((uint32_t)(row * 128 + q * 8));
    }

    // ---- warp tiling: 2 (row) x 2 (col) x 2 (k-half); 32x32 per warp ----
    const int wk = wid >> 2;          // k-half: ks in {2wk, 2wk+1}
    const int wr = (wid >> 1) & 1;
    const int wc = wid & 1;
    const int r0 = wr * 32;
    const int c0 = wc * 32;

    const uint32_t s0 = smem_u32(dsmem);
    const int arow0 = r0 + (lane & 15);
    const int bcol0 = c0 + (lane & 15);
    const uint32_t axm   = (uint32_t)((arow0 & 7) * 16);  // same for arow0+16
    const uint32_t bxm   = (uint32_t)((bcol0 & 7) * 16);
    const uint32_t khalf = (uint32_t)((lane >> 4) * 16);

    const uint32_t aoff0 = (uint32_t)(arow0 * 128);
    const uint32_t aoff1 = (uint32_t)((arow0 + 16) * 128);
    const uint32_t boff0 = (uint32_t)(bcol0 * 128);
    const uint32_t boff1 = (uint32_t)((bcol0 + 16) * 128);

    float acc[2][4][4];
#pragma unroll
    for (int m = 0; m < 2; ++m)
#pragma unroll
        for (int n = 0; n < 4; ++n)
#pragma unroll
            for (int f = 0; f < 4; ++f) acc[m][n][f] = 0.0f;

    // Prefetch tile 0.
    float4 rx[4], rw[4];
#pragma unroll
    for (int i = 0; i < 4; ++i) {
        rx[i] = *(const float4*)(px[i]);
        rw[i] = *(const float4*)(pw[i]);
    }

    for (int t = 0; t < cnt; ++t) {
        const uint32_t bufo = (uint32_t)(t & 1) * BUF_BYTES;
        char* buf = dsmem + bufo;

        // Store tile t (convert f32 -> bf16 hi/lo).
#pragma unroll
        for (int i = 0; i < 4; ++i) {
            uint2 hi, lo;
            split4(rx[i], hi, lo);
            *(uint2*)(buf + XH_OFF + soff[i]) = hi;
            *(uint2*)(buf + XL_OFF + soff[i]) = lo;
            split4(rw[i], hi, lo);
            *(uint2*)(buf + WH_OFF + soff[i]) = hi;
            *(uint2*)(buf + WL_OFF + soff[i]) = lo;
        }
        __syncthreads();   // single barrier per tile

        // Prefetch tile t+1 (overlaps the mma compute below).
        if (t + 1 < cnt) {
            const long off = (long)(t + 1) * TILE_K;
#pragma unroll
            for (int i = 0; i < 4; ++i) {
                rx[i] = *(const float4*)(px[i] + off);
                rw[i] = *(const float4*)(pw[i] + off);
            }
        }

        // Compute this warp's k-half on buffer t&1.
        const uint32_t sb = s0 + bufo;
#pragma unroll
        for (int s = 0; s < 2; ++s) {
            const uint32_t kterm = (uint32_t)((2 * wk + s) * 32) + khalf;
            const uint32_t ka = kterm ^ axm;
            const uint32_t kb = kterm ^ bxm;

            uint32_t ah0[4], ah1[4], al0[4], al1[4];
            uint32_t bha[4], bhb[4], bla[4], blb[4];
            ldsm4(ah0, sb + XH_OFF + aoff0 + ka);
            ldsm4(ah1, sb + XH_OFF + aoff1 + ka);
            ldsm4(bha, sb + WH_OFF + boff0 + kb);
            ldsm4(bhb, sb + WH_OFF + boff1 + kb);
            ldsm4(al0, sb + XL_OFF + aoff0 + ka);
            ldsm4(al1, sb + XL_OFF + aoff1 + ka);
            ldsm4(bla, sb + WL_OFF + boff0 + kb);
            ldsm4(blb, sb + WL_OFF + boff1 + kb);

            // term hh
            mma16816(acc[0][0], ah0, bha[0], bha[2]);
            mma16816(acc[0][1], ah0, bha[1], bha[3]);
            mma16816(acc[0][2], ah0, bhb[0], bhb[2]);
            mma16816(acc[0][3], ah0, bhb[1], bhb[3]);
            mma16816(acc[1][0], ah1, bha[0], bha[2]);
            mma16816(acc[1][1], ah1, bha[1], bha[3]);
            mma16816(acc[1][2], ah1, bhb[0], bhb[2]);
            mma16816(acc[1][3], ah1, bhb[1], bhb[3]);
            // term hl
            mma16816(acc[0][0], ah0, bla[0], bla[2]);
            mma16816(acc[0][1], ah0, bla[1], bla[3]);
            mma16816(acc[0][2], ah0, blb[0], blb[2]);
            mma16816(acc[0][3], ah0, blb[1], blb[3]);
            mma16816(acc[1][0], ah1, bla[0], bla[2]);
            mma16816(acc[1][1], ah1, bla[1], bla[3]);
            mma16816(acc[1][2], ah1, blb[0], blb[2]);
            mma16816(acc[1][3], ah1, blb[1], blb[3]);
            // term lh
            mma16816(acc[0][0], al0, bha[0], bha[2]);
            mma16816(acc[0][1], al0, bha[1], bha[3]);
            mma16816(acc[0][2], al0, bhb[0], bhb[2]);
            mma16816(acc[0][3], al0, bhb[1], bhb[3]);
            mma16816(acc[1][0], al1, bha[0], bha[2]);
            mma16816(acc[1][1], al1, bha[1], bha[3]);
            mma16816(acc[1][2], al1, bhb[0], bhb[2]);
            mma16816(acc[1][3], al1, bhb[1], bhb[3]);
        }
    }

    // ---- epilogue: merge the two k-half accumulator sets, write partials ----
    __syncthreads();                      // mainloop reads done; reuse smem
    float* ebuf = (float*)dsmem;          // 64x64 f32 = 16KB

    const int gr = lane >> 2;
    const int gc = (lane & 3) * 2;

    if (wk == 1) {
#pragma unroll
        for (int m = 0; m < 2; ++m)
#pragma unroll
            for (int n = 0; n < 4; ++n) {
                const int rr = r0 + m * 16 + gr;
                const int cc = c0 + n * 8 + gc;
                *(float2*)&ebuf[rr * 64 + cc] =
                    make_float2(acc[m][n][0], acc[m][n][1]);
                *(float2*)&ebuf[(rr + 8) * 64 + cc] =
                    make_float2(acc[m][n][2], acc[m][n][3]);
            }
    }
    __syncthreads();

    if (wk == 0) {
        float* dst = g_partials + (long)bid * 4096;
#pragma unroll
        for (int m = 0; m < 2; ++m)
#pragma unroll
            for (int n = 0; n < 4; ++n) {
                const int rr = r0 + m * 16 + gr;
                const int cc = c0 + n * 8 + gc;
                float2 e0 = *(float2*)&ebuf[rr * 64 + cc];
                float2 e1 = *(float2*)&ebuf[(rr + 8) * 64 + cc];
                *(float2*)&dst[rr * 64 + cc] =
                    make_float2(acc[m][n][0] + e0.x, acc[m][n][1] + e0.y);
                *(float2*)&dst[(rr + 8) * 64 + cc] =
                    make_float2(acc[m][n][2] + e1.x, acc[m][n][3] + e1.y);
            }
    }
}

// ---------------- Finalize: reduce + bias + top-k + softmax ----------------

__global__ __launch_bounds__(1024) void finalize_kernel(
    const float* __restrict__ bias, const int* __restrict__ kp,
    float* __restrict__ out) {
    const int b    = blockIdx.x;    // batch row
    const int t    = threadIdx.x;   // 1024 threads
    const int e    = t & 63;        // expert
    const int part = t >> 6;        // 0..15

    float sum = 0.0f;
    const float* p = g_partials + b * 64 + e;
#pragma unroll 4
    for (int i = part; i < NBLK; i += 16)
        sum += p[(long)i * 4096];

    __shared__ float acc[16][64];
    __shared__ float ys[64];
    __shared__ float evs[64];

    acc[part][e] = sum;
    __syncthreads();
    if (part == 0) {
        float s2 = 0.0f;
#pragma unroll
        for (int j = 0; j < 16; ++j) s2 += acc[j][e];
        ys[e] = s2 + bias[e];
    }
    __syncthreads();

    const float yv = ys[e];
    const int kk = *kp;
    int rank = 0;
#pragma unroll 8
    for (int j = 0; j < 64; ++j) {
        const float yj = ys[j];
        rank += (yj > yv) || (yj == yv && j < e);
    }
    const float ev = (rank < kk) ? expf(yv) : 1.0f;
    if (part == 0) evs[e] = ev;
    __syncthreads();

    for (int off = 32; off > 0; off >>= 1) {
        if (t < off) evs[t] += evs[t + off];
        __syncthreads();
    }
    const float denom = evs[0];

    if (part == 0) out[b * 64 + e] = ev / denom;
}

extern "C" void kernel_launch(void* const* d_in, const int* in_sizes, int n_in,
                              void* d_out, int out_size) {
    const float* x    = (const float*)d_in[0];
    const float* W    = (const float*)d_in[1];
    const float* bias = (const float*)d_in[2];
    const int*   kp   = (const int*)d_in[3];
    float* out = (float*)d_out;

    cudaFuncSetAttribute(gemm_mma_kernel,
                         cudaFuncAttributeMaxDynamicSharedMemorySize,
                         2 * BUF_BYTES);
    gemm_mma_kernel<<<NBLK, 256, 2 * BUF_BYTES>>>(x, W);
    finalize_kernel<<<64, 1024>>>(bias, kp, out);
}